// round 1
// baseline (speedup 1.0000x reference)
#include <cuda_runtime.h>

// LIF recurrence, forward spikes only.
// x: [T, B, D] fp32, out: [T, B, D] fp32 (0.0/1.0)
// mem_t = mem_{t-1} * DECAY * (1 - spike_{t-1}) + x_t ; spike_t = (mem_t > THRESH)
// Each (b,d) chain is independent -> thread handles 4 consecutive chains (float4),
// strided by BD/4 across the T dimension. Pure HBM streaming kernel.

#define THRESH 0.5f
#define DECAY  0.25f

__global__ __launch_bounds__(256) void lif_kernel(
    const float4* __restrict__ x,
    float4* __restrict__ out,
    int chains4,   // BD / 4
    int T)
{
    int i = blockIdx.x * blockDim.x + threadIdx.x;
    if (i >= chains4) return;

    // t = 0
    float4 mem = x[i];
    float4 s;
    s.x = (mem.x > THRESH) ? 1.0f : 0.0f;
    s.y = (mem.y > THRESH) ? 1.0f : 0.0f;
    s.z = (mem.z > THRESH) ? 1.0f : 0.0f;
    s.w = (mem.w > THRESH) ? 1.0f : 0.0f;
    out[i] = s;

    long idx = i;
    #pragma unroll 4
    for (int t = 1; t < T; t++) {
        idx += chains4;
        float4 xt = x[idx];
        // mem = mem * DECAY * (1 - s) + xt ; note s in {0,1} so (1-s) zeroes or keeps
        mem.x = mem.x * (DECAY * (1.0f - s.x)) + xt.x;
        mem.y = mem.y * (DECAY * (1.0f - s.y)) + xt.y;
        mem.z = mem.z * (DECAY * (1.0f - s.z)) + xt.z;
        mem.w = mem.w * (DECAY * (1.0f - s.w)) + xt.w;
        s.x = (mem.x > THRESH) ? 1.0f : 0.0f;
        s.y = (mem.y > THRESH) ? 1.0f : 0.0f;
        s.z = (mem.z > THRESH) ? 1.0f : 0.0f;
        s.w = (mem.w > THRESH) ? 1.0f : 0.0f;
        out[idx] = s;
    }
}

extern "C" void kernel_launch(void* const* d_in, const int* in_sizes, int n_in,
                              void* d_out, int out_size)
{
    const float* x = (const float*)d_in[0];
    float* out = (float*)d_out;

    const int T = 32;
    int total = in_sizes[0];        // T * B * D
    int BD = total / T;             // 1,048,576
    int chains4 = BD / 4;           // 262,144

    int threads = 256;
    int blocks = (chains4 + threads - 1) / threads;
    lif_kernel<<<blocks, threads>>>((const float4*)x, (float4*)out, chains4, T);
}

// round 2
// speedup vs baseline: 1.0956x; 1.0956x over previous
#include <cuda_runtime.h>

// LIF recurrence, forward spikes only.
// x: [T, B, D] fp32, out: [T, B, D] fp32 (0.0/1.0)
// mem_t = mem_{t-1} * DECAY * (1 - spike_{t-1}) + x_t ; spike_t = (mem_t > THRESH)
//
// Pure touch-once HBM stream (128 MB in + 128 MB out). Strategy:
//  - one float4 chain per thread, T-loop in chunks of 8 with ALL 8 loads
//    hoisted up front (__ldcs streaming: no L2 reuse exists) -> MLP = 8/warp
//  - __stcs streaming stores (write-once output, avoid L2 write-allocate)

#define THRESH 0.5f
#define DECAY  0.25f

__device__ __forceinline__ float4 lif_step(float4 mem, float4 s, float4 xt,
                                           float4* s_out)
{
    float4 m;
    m.x = mem.x * (DECAY * (1.0f - s.x)) + xt.x;
    m.y = mem.y * (DECAY * (1.0f - s.y)) + xt.y;
    m.z = mem.z * (DECAY * (1.0f - s.z)) + xt.z;
    m.w = mem.w * (DECAY * (1.0f - s.w)) + xt.w;
    s_out->x = (m.x > THRESH) ? 1.0f : 0.0f;
    s_out->y = (m.y > THRESH) ? 1.0f : 0.0f;
    s_out->z = (m.z > THRESH) ? 1.0f : 0.0f;
    s_out->w = (m.w > THRESH) ? 1.0f : 0.0f;
    return m;
}

__global__ __launch_bounds__(256) void lif_kernel(
    const float4* __restrict__ x,
    float4* __restrict__ out,
    int chains4)   // BD / 4
{
    int i = blockIdx.x * blockDim.x + threadIdx.x;
    if (i >= chains4) return;

    // t = 0
    float4 mem = __ldcs(&x[i]);
    float4 s;
    s.x = (mem.x > THRESH) ? 1.0f : 0.0f;
    s.y = (mem.y > THRESH) ? 1.0f : 0.0f;
    s.z = (mem.z > THRESH) ? 1.0f : 0.0f;
    s.w = (mem.w > THRESH) ? 1.0f : 0.0f;
    __stcs(&out[i], s);

    // t = 1..7 : first partial chunk (7 hoisted loads)
    {
        float4 xt[7];
        #pragma unroll
        for (int k = 0; k < 7; k++)
            xt[k] = __ldcs(&x[i + (long)(1 + k) * chains4]);
        #pragma unroll
        for (int k = 0; k < 7; k++) {
            mem = lif_step(mem, s, xt[k], &s);
            __stcs(&out[i + (long)(1 + k) * chains4], s);
        }
    }

    // t = 8..31 : chunks of 8 hoisted loads
    #pragma unroll 1
    for (int t0 = 8; t0 < 32; t0 += 8) {
        float4 xt[8];
        #pragma unroll
        for (int k = 0; k < 8; k++)
            xt[k] = __ldcs(&x[i + (long)(t0 + k) * chains4]);
        #pragma unroll
        for (int k = 0; k < 8; k++) {
            mem = lif_step(mem, s, xt[k], &s);
            __stcs(&out[i + (long)(t0 + k) * chains4], s);
        }
    }
}

extern "C" void kernel_launch(void* const* d_in, const int* in_sizes, int n_in,
                              void* d_out, int out_size)
{
    const float* x = (const float*)d_in[0];
    float* out = (float*)d_out;

    const int T = 32;
    int total = in_sizes[0];        // T * B * D
    int BD = total / T;             // 1,048,576
    int chains4 = BD / 4;           // 262,144

    int threads = 256;
    int blocks = (chains4 + threads - 1) / threads;
    lif_kernel<<<blocks, threads>>>((const float4*)x, (float4*)out, chains4);
}